// round 1
// baseline (speedup 1.0000x reference)
#include <cuda_runtime.h>

// ---------------------------------------------------------------------------
// HierarchicalMemory: out = softmax_m( mask( (qn . mkn)/T ) ) @ V @ Wo^T + bo
// with q = X@Wk^T + bk, qn = l2ish(q), mkn = l2ish(mem_keys).
// Since |qn.mkn| <= 1, logits in [-10,10]: softmax computed with FIXED offset
//   P = exp(s - 10) (masked -> 0),  w = P / rowsum(P).
// Pipeline (all fp32, round-1 baseline):
//   K1 row_l2norm(mem_keys) -> g_mkn
//   K2 gemm_nt  q = X @ Wk^T + bk            -> g_q
//   K3 row_qscale: g_qs[m] = rsqrt(sum q^2 + eps) * 10
//   K4 gemm_nt  P = mask ? exp(dot*qs - 10) : 0   -> g_P  [8192 x 16384]
//   K5 row_invsum: g_ir[m] = 1 / sum_n P[m,n]
//   K6 gemm_nn  ret = (P @ V) * g_ir[m]      -> g_ret
//   K7 gemm_nt  out = ret @ Wo^T + bo        -> d_out
// ---------------------------------------------------------------------------

#define BM 128
#define BN 128
#define BK 8

#define MQ 8192
#define HD 1024
#define MMSZ 16384

// scratch (device globals: allocation-free per harness rules)
__device__ float g_mkn[(size_t)MMSZ * HD];
__device__ float g_q[(size_t)MQ * HD];
__device__ float g_qs[MQ];
__device__ float g_P[(size_t)MQ * MMSZ];
__device__ float g_ir[MQ];
__device__ float g_ret[(size_t)MQ * HD];

enum { EPI_BIAS = 0, EPI_EXPMASK = 1, EPI_ROWSCALE = 2 };

__device__ __forceinline__ float block_reduce_sum_256(float v) {
    // full warp reduce
    #pragma unroll
    for (int o = 16; o > 0; o >>= 1) v += __shfl_xor_sync(0xffffffffu, v, o);
    __shared__ float sm[8];
    int w = threadIdx.x >> 5, l = threadIdx.x & 31;
    if (l == 0) sm[w] = v;
    __syncthreads();
    float r = 0.0f;
    if (w == 0) {
        r = (l < 8) ? sm[l] : 0.0f;
        #pragma unroll
        for (int o = 4; o > 0; o >>= 1) r += __shfl_xor_sync(0xffffffffu, r, o);
    }
    return r;  // valid on thread 0
}

// one block per row, H = 1024, 256 threads: 1 float4 per thread
__global__ void row_l2norm(const float* __restrict__ in, float* __restrict__ out) {
    size_t base = (size_t)blockIdx.x * HD + threadIdx.x * 4;
    float4 v = *(const float4*)(in + base);
    float s = v.x * v.x + v.y * v.y + v.z * v.z + v.w * v.w;
    s = block_reduce_sum_256(s);
    __shared__ float sc;
    if (threadIdx.x == 0) sc = rsqrtf(s + 1e-6f);
    __syncthreads();
    float k = sc;
    v.x *= k; v.y *= k; v.z *= k; v.w *= k;
    *(float4*)(out + base) = v;
}

// per-row combined scale: rsqrt(sumsq + eps) / TEMPERATURE  (T = 0.1 -> *10)
__global__ void row_qscale(const float* __restrict__ q, float* __restrict__ scale) {
    size_t base = (size_t)blockIdx.x * HD + threadIdx.x * 4;
    float4 v = *(const float4*)(q + base);
    float s = v.x * v.x + v.y * v.y + v.z * v.z + v.w * v.w;
    s = block_reduce_sum_256(s);
    if (threadIdx.x == 0) scale[blockIdx.x] = rsqrtf(s + 1e-6f) * 10.0f;
}

// inverse row sum of P, row length MMSZ
__global__ void row_invsum(const float* __restrict__ P, float* __restrict__ inv) {
    const float4* p = (const float4*)(P + (size_t)blockIdx.x * MMSZ);
    float s = 0.0f;
    #pragma unroll 4
    for (int i = threadIdx.x; i < MMSZ / 4; i += 256) {
        float4 v = p[i];
        s += v.x + v.y + v.z + v.w;
    }
    s = block_reduce_sum_256(s);
    if (threadIdx.x == 0) inv[blockIdx.x] = 1.0f / s;
}

// ---------------------------------------------------------------------------
// C[M,N] = A[M,K] * op(B) with fused epilogue.
//   BT=true : B is [N,K] row-major (NT gemm, dot over contiguous K)
//   BT=false: B is [K,N] row-major (NN gemm)
// aux: bias[N] (EPI_BIAS) or per-row scale[M] (EPI_EXPMASK / EPI_ROWSCALE)
// usage: mask (EPI_EXPMASK)
// Requires M%128==0, N%128==0, K%8==0.
// ---------------------------------------------------------------------------
template <int EPI, bool BT>
__global__ __launch_bounds__(256, 2)
void gemm128(const float* __restrict__ A, const float* __restrict__ B,
             float* __restrict__ C, int M, int N, int K,
             const float* __restrict__ aux, const int* __restrict__ usage) {
    __shared__ float As[BK][BM];
    __shared__ float Bs[BK][BN];

    const int tid = threadIdx.x;
    const int m0 = blockIdx.y * BM;
    const int n0 = blockIdx.x * BN;

    // global-load mappings
    const int ar = tid >> 1;            // 0..127 (row within tile, NT loads)
    const int ak = (tid & 1) * 4;       // k-half
    const int bkr = tid >> 5;           // 0..7  (k-row, NN loads)
    const int bc = (tid & 31) * 4;      // 0..124 (col group, NN loads)

    const int tx = tid & 15;            // 0..15 -> 8 output cols each
    const int ty = tid >> 4;            // 0..15 -> 8 output rows each

    float acc[8][8];
    #pragma unroll
    for (int i = 0; i < 8; i++)
        #pragma unroll
        for (int j = 0; j < 8; j++) acc[i][j] = 0.0f;

    const float* Aptr = A + (size_t)(m0 + ar) * K + ak;
    const float* Bptr = BT ? (B + (size_t)(n0 + ar) * K + ak)
                           : (B + (size_t)bkr * N + n0 + bc);

    for (int kt = 0; kt < K; kt += BK) {
        float4 av = *(const float4*)(Aptr + kt);
        float4 bv;
        if (BT) bv = *(const float4*)(Bptr + kt);
        else    bv = *(const float4*)(Bptr + (size_t)kt * N);

        __syncthreads();
        As[ak + 0][ar] = av.x; As[ak + 1][ar] = av.y;
        As[ak + 2][ar] = av.z; As[ak + 3][ar] = av.w;
        if (BT) {
            Bs[ak + 0][ar] = bv.x; Bs[ak + 1][ar] = bv.y;
            Bs[ak + 2][ar] = bv.z; Bs[ak + 3][ar] = bv.w;
        } else {
            *(float4*)&Bs[bkr][bc] = bv;
        }
        __syncthreads();

        #pragma unroll
        for (int k = 0; k < BK; k++) {
            float4 a0 = *(const float4*)&As[k][ty * 8];
            float4 a1 = *(const float4*)&As[k][ty * 8 + 4];
            float4 b0 = *(const float4*)&Bs[k][tx * 8];
            float4 b1 = *(const float4*)&Bs[k][tx * 8 + 4];
            float a[8] = {a0.x, a0.y, a0.z, a0.w, a1.x, a1.y, a1.z, a1.w};
            float b[8] = {b0.x, b0.y, b0.z, b0.w, b1.x, b1.y, b1.z, b1.w};
            #pragma unroll
            for (int i = 0; i < 8; i++)
                #pragma unroll
                for (int j = 0; j < 8; j++)
                    acc[i][j] = fmaf(a[i], b[j], acc[i][j]);
        }
    }

    // ---- epilogue ----
    const int nc = n0 + tx * 8;
    float bias[8];
    int msk[8];
    if (EPI == EPI_BIAS) {
        float4 b0 = *(const float4*)(aux + nc);
        float4 b1 = *(const float4*)(aux + nc + 4);
        bias[0] = b0.x; bias[1] = b0.y; bias[2] = b0.z; bias[3] = b0.w;
        bias[4] = b1.x; bias[5] = b1.y; bias[6] = b1.z; bias[7] = b1.w;
    }
    if (EPI == EPI_EXPMASK) {
        int4 u0 = *(const int4*)(usage + nc);
        int4 u1 = *(const int4*)(usage + nc + 4);
        msk[0] = u0.x; msk[1] = u0.y; msk[2] = u0.z; msk[3] = u0.w;
        msk[4] = u1.x; msk[5] = u1.y; msk[6] = u1.z; msk[7] = u1.w;
    }

    #pragma unroll
    for (int i = 0; i < 8; i++) {
        const int m = m0 + ty * 8 + i;
        float rs = (EPI != EPI_BIAS) ? aux[m] : 0.0f;
        float* crow = C + (size_t)m * N + nc;
        float r[8];
        #pragma unroll
        for (int j = 0; j < 8; j++) {
            float v = acc[i][j];
            if (EPI == EPI_BIAS)     v += bias[j];
            if (EPI == EPI_EXPMASK)  v = (msk[j] > 0) ? __expf(v * rs - 10.0f) : 0.0f;
            if (EPI == EPI_ROWSCALE) v *= rs;
            r[j] = v;
        }
        float4 o0 = {r[0], r[1], r[2], r[3]};
        float4 o1 = {r[4], r[5], r[6], r[7]};
        *(float4*)(crow)     = o0;
        *(float4*)(crow + 4) = o1;
    }
}

// ---------------------------------------------------------------------------

extern "C" void kernel_launch(void* const* d_in, const int* in_sizes, int n_in,
                              void* d_out, int out_size) {
    const float* hidden = (const float*)d_in[0];
    const float* Wk     = (const float*)d_in[1];
    const float* bk     = (const float*)d_in[2];
    // d_in[3], d_in[4] = Wv, bv : unused by the reference
    const float* Wo     = (const float*)d_in[5];
    const float* bo     = (const float*)d_in[6];
    const float* mkeys  = (const float*)d_in[7];
    const float* mvals  = (const float*)d_in[8];
    const int*   usage  = (const int*)d_in[9];

    float *mkn, *q, *qs, *P, *ir, *ret;
    cudaGetSymbolAddress((void**)&mkn, g_mkn);
    cudaGetSymbolAddress((void**)&q,   g_q);
    cudaGetSymbolAddress((void**)&qs,  g_qs);
    cudaGetSymbolAddress((void**)&P,   g_P);
    cudaGetSymbolAddress((void**)&ir,  g_ir);
    cudaGetSymbolAddress((void**)&ret, g_ret);

    // K1: normalize memory keys
    row_l2norm<<<MMSZ, 256>>>(mkeys, mkn);

    // K2: q = X @ Wk^T + bk
    gemm128<EPI_BIAS, true><<<dim3(HD / BN, MQ / BM), 256>>>(
        hidden, Wk, q, MQ, HD, HD, bk, nullptr);

    // K3: per-row query scale (rsqrt(sumsq+eps)/T)
    row_qscale<<<MQ, 256>>>(q, qs);

    // K4: P = mask ? exp((q . mkn) * qs - 10) : 0
    gemm128<EPI_EXPMASK, true><<<dim3(MMSZ / BN, MQ / BM), 256>>>(
        q, mkn, P, MQ, MMSZ, HD, qs, usage);

    // K5: inverse row sums
    row_invsum<<<MQ, 256>>>(P, ir);

    // K6: ret = (P @ V) * inv_rowsum
    gemm128<EPI_ROWSCALE, false><<<dim3(HD / BN, MQ / BM), 256>>>(
        P, mvals, ret, MQ, HD, MMSZ, ir, nullptr);

    // K7: out = ret @ Wo^T + bo
    gemm128<EPI_BIAS, true><<<dim3(HD / BN, MQ / BM), 256>>>(
        ret, Wo, (float*)d_out, MQ, HD, HD, bo, nullptr);
}

// round 4
// speedup vs baseline: 2.0216x; 2.0216x over previous
#include <cuda_runtime.h>
#include <cstdint>

// ===========================================================================
// HierarchicalMemory via mma.sync tf32 (HMMA) — sm_103 base target safe.
//   out = softmax_m(mask(qn.mkn/T)) @ V @ Wo^T + bo,  q = X@Wk^T + bk
// Fixed-offset softmax (|logit|<=10): P = exp(s-10), w = P/rowsum.
// All GEMM operands pre-rounded to tf32 (cvt.rna) -> HMMA truncation exact.
// ===========================================================================

#define MQ   8192
#define HD   1024
#define MMSZ 16384

#define BM 128
#define BN 128
#define BK 16
#define STAGES 3
#define RSTRIDE 20                       // words per smem row (conflict-free)
#define ATILE_B (BM * RSTRIDE * 4)       // 10240 B
#define STAGE_B (2 * ATILE_B)            // A + B
#define SMEM_TOTAL (STAGES * STAGE_B)    // 61440 B

// ---- scratch ----
__device__ float g_mkn[(size_t)MMSZ * HD];
__device__ float g_q  [(size_t)MQ * HD];
__device__ float g_qs [MQ];
__device__ float g_P  [(size_t)MQ * MMSZ];
__device__ float g_rs [MQ];
__device__ float g_ret[(size_t)MQ * HD];
__device__ float g_vt [(size_t)HD * MMSZ];
__device__ float g_ht [(size_t)MQ * HD];
__device__ float g_wk [(size_t)HD * HD];
__device__ float g_wo [(size_t)HD * HD];

enum { EPI_BIAS = 0, EPI_EXPMASK = 1, EPI_ROWSCALE = 2 };

// ---------------------------------------------------------------------------
__device__ __forceinline__ uint32_t smem_u32(const void* p) {
    uint32_t a;
    asm("{ .reg .u64 t; cvta.to.shared.u64 t, %1; cvt.u32.u64 %0, t; }" : "=r"(a) : "l"(p));
    return a;
}
__device__ __forceinline__ float to_tf32(float x) {
    uint32_t u;
    asm("cvt.rna.tf32.f32 %0, %1;" : "=r"(u) : "f"(x));
    return __uint_as_float(u);
}
#define CP_ASYNC16(dst, src) \
    asm volatile("cp.async.cg.shared.global [%0], [%1], 16;" :: "r"(dst), "l"(src) : "memory")
#define CP_COMMIT() asm volatile("cp.async.commit_group;" ::: "memory")
#define CP_WAIT1()  asm volatile("cp.async.wait_group 1;" ::: "memory")

__device__ __forceinline__ void mma8(float* d, const uint32_t* a, const uint32_t* b) {
    asm volatile(
        "mma.sync.aligned.m16n8k8.row.col.f32.tf32.tf32.f32 "
        "{%0,%1,%2,%3}, {%4,%5,%6,%7}, {%8,%9}, {%0,%1,%2,%3};"
        : "+f"(d[0]), "+f"(d[1]), "+f"(d[2]), "+f"(d[3])
        : "r"(a[0]), "r"(a[1]), "r"(a[2]), "r"(a[3]), "r"(b[0]), "r"(b[1]));
}

// ---------------------------------------------------------------------------
// C[M,N] = A[M,K] . B[N,K]^T   (NT, both K-major, tf32-rounded fp32)
// nx=1: blockIdx.x -> n-tile (for L2 reuse of A in K6)
// ---------------------------------------------------------------------------
template <int EPI, bool ROUND>
__global__ __launch_bounds__(256)
void gemm_mma(const float* __restrict__ A, const float* __restrict__ B,
              float* __restrict__ C, int M, int N, int K,
              const float* __restrict__ aux, const int* __restrict__ usage,
              float* __restrict__ rowsum, int nx) {
    extern __shared__ char smem[];
    const uint32_t sb = smem_u32(smem);
    const int tid  = threadIdx.x;
    const int wid  = tid >> 5, lane = tid & 31;
    const int g    = lane >> 2, t = lane & 3;
    const int wm   = wid >> 2, wn = wid & 3;        // warp grid 2 x 4 (64x32 tiles)

    const int mtb = nx ? blockIdx.y : blockIdx.x;
    const int ntb = nx ? blockIdx.x : blockIdx.y;
    const int m0 = mtb * BM, n0 = ntb * BN;
    const int n_it = K / BK;

    const int lrow = tid >> 2;      // 0..63
    const int lq   = tid & 3;       // 16B chunk within 64B row half

    float acc[4][4][4];
    #pragma unroll
    for (int i = 0; i < 4; i++)
        #pragma unroll
        for (int j = 0; j < 4; j++)
            #pragma unroll
            for (int r = 0; r < 4; r++) acc[i][j][r] = 0.0f;

    // ---- async loader for one k-slab (it) ----
    auto issue = [&](int it) {
        if (it < n_it) {
            const int s = it % STAGES;
            const int kt = it * BK;
            const uint32_t da = sb + s * STAGE_B;
            const uint32_t db = da + ATILE_B;
            const float* ga = A + (size_t)m0 * K + kt;
            const float* gb = B + (size_t)n0 * K + kt;
            #pragma unroll
            for (int p = 0; p < 2; p++) {
                const int row = lrow + p * 64;
                CP_ASYNC16(da + row * (RSTRIDE * 4) + lq * 16, ga + (size_t)row * K + lq * 4);
                CP_ASYNC16(db + row * (RSTRIDE * 4) + lq * 16, gb + (size_t)row * K + lq * 4);
            }
        }
        CP_COMMIT();
    };

    issue(0);
    issue(1);
    CP_WAIT1();           // group 0 done
    __syncthreads();

    for (int it = 0; it < n_it; ++it) {
        issue(it + 2);    // writes slot (it-1)%3, consumed before prior barrier

        const int s = it % STAGES;
        const uint32_t* As = (const uint32_t*)(smem + s * STAGE_B);
        const uint32_t* Bs = (const uint32_t*)(smem + s * STAGE_B + ATILE_B);

        #pragma unroll
        for (int kk = 0; kk < 2; kk++) {
            const int ko = kk * 8 + t;
            uint32_t af[4][4], bf[4][2];
            #pragma unroll
            for (int mt = 0; mt < 4; mt++) {
                const int base = (wm * 64 + mt * 16 + g) * RSTRIDE + ko;
                af[mt][0] = As[base];
                af[mt][1] = As[base + 8 * RSTRIDE];
                af[mt][2] = As[base + 4];
                af[mt][3] = As[base + 8 * RSTRIDE + 4];
            }
            #pragma unroll
            for (int nt = 0; nt < 4; nt++) {
                const int base = (wn * 32 + nt * 8 + g) * RSTRIDE + ko;
                bf[nt][0] = Bs[base];
                bf[nt][1] = Bs[base + 4];
            }
            #pragma unroll
            for (int mt = 0; mt < 4; mt++)
                #pragma unroll
                for (int nt = 0; nt < 4; nt++)
                    mma8(acc[mt][nt], af[mt], bf[nt]);
        }

        CP_WAIT1();       // next compute stage resident for this thread
        __syncthreads();  // ...for all threads; also fences reads of slot it
    }

    // ---------------- epilogue ----------------
    const int mrow = m0 + wm * 64;
    const int ncol = n0 + wn * 32;

    // per-column data (bias / mask), per 8-col tile, 2 cols per thread
    float bia[4][2];
    int msk[4][2];
    #pragma unroll
    for (int nt = 0; nt < 4; nt++) {
        const int c = ncol + nt * 8 + 2 * t;
        if (EPI == EPI_BIAS) { bia[nt][0] = __ldg(aux + c); bia[nt][1] = __ldg(aux + c + 1); }
        if (EPI == EPI_EXPMASK) { msk[nt][0] = __ldg(usage + c); msk[nt][1] = __ldg(usage + c + 1); }
    }
    // per-row scale, 8 rows per thread
    float rsv[4][2];
    #pragma unroll
    for (int mt = 0; mt < 4; mt++)
        #pragma unroll
        for (int h = 0; h < 2; h++) {
            const int r = mrow + mt * 16 + g + h * 8;
            if (EPI == EPI_EXPMASK)  rsv[mt][h] = __ldg(aux + r);
            if (EPI == EPI_ROWSCALE) rsv[mt][h] = 1.0f / __ldg(aux + r);
        }

    float rsum[4][2];
    #pragma unroll
    for (int mt = 0; mt < 4; mt++) { rsum[mt][0] = 0.0f; rsum[mt][1] = 0.0f; }

    #pragma unroll
    for (int mt = 0; mt < 4; mt++) {
        #pragma unroll
        for (int h = 0; h < 2; h++) {
            const int r = mrow + mt * 16 + g + h * 8;
            float* crow = C + (size_t)r * N;
            #pragma unroll
            for (int nt = 0; nt < 4; nt++) {
                const int c = ncol + nt * 8 + 2 * t;
                float v0 = acc[mt][nt][2 * h + 0];
                float v1 = acc[mt][nt][2 * h + 1];
                if (EPI == EPI_BIAS) { v0 += bia[nt][0]; v1 += bia[nt][1]; }
                if (EPI == EPI_EXPMASK) {
                    const float rs = rsv[mt][h];
                    v0 = (msk[nt][0] > 0) ? __expf(fmaf(v0, rs, -10.0f)) : 0.0f;
                    v1 = (msk[nt][1] > 0) ? __expf(fmaf(v1, rs, -10.0f)) : 0.0f;
                }
                if (EPI == EPI_ROWSCALE) { v0 *= rsv[mt][h]; v1 *= rsv[mt][h]; }
                if (ROUND) { v0 = to_tf32(v0); v1 = to_tf32(v1); }
                if (EPI == EPI_EXPMASK) rsum[mt][h] += v0 + v1;
                *(float2*)(crow + c) = make_float2(v0, v1);
            }
        }
    }

    if (EPI == EPI_EXPMASK) {
        #pragma unroll
        for (int mt = 0; mt < 4; mt++)
            #pragma unroll
            for (int h = 0; h < 2; h++) {
                float v = rsum[mt][h];
                v += __shfl_xor_sync(0xffffffffu, v, 1);
                v += __shfl_xor_sync(0xffffffffu, v, 2);
                if (t == 0) atomicAdd(rowsum + mrow + mt * 16 + g + h * 8, v);
            }
    }
}

// ---------------------------------------------------------------------------
// aux kernels
// ---------------------------------------------------------------------------
__device__ __forceinline__ float blk_reduce_256(float v) {
    #pragma unroll
    for (int o = 16; o > 0; o >>= 1) v += __shfl_xor_sync(0xffffffffu, v, o);
    __shared__ float sm[8];
    int w = threadIdx.x >> 5, l = threadIdx.x & 31;
    if (l == 0) sm[w] = v;
    __syncthreads();
    float r = 0.0f;
    if (w == 0) {
        r = (l < 8) ? sm[l] : 0.0f;
        #pragma unroll
        for (int o = 4; o > 0; o >>= 1) r += __shfl_xor_sync(0xffffffffu, r, o);
    }
    return r;
}

__global__ void row_l2norm_rnd(const float* __restrict__ in, float* __restrict__ out) {
    size_t base = (size_t)blockIdx.x * HD + threadIdx.x * 4;
    float4 v = *(const float4*)(in + base);
    float s = v.x * v.x + v.y * v.y + v.z * v.z + v.w * v.w;
    s = blk_reduce_256(s);
    __shared__ float sc;
    if (threadIdx.x == 0) sc = rsqrtf(s + 1e-6f);
    __syncthreads();
    float k = sc;
    v.x = to_tf32(v.x * k); v.y = to_tf32(v.y * k);
    v.z = to_tf32(v.z * k); v.w = to_tf32(v.w * k);
    *(float4*)(out + base) = v;
}

__global__ void row_qscale(const float* __restrict__ q, float* __restrict__ scale) {
    size_t base = (size_t)blockIdx.x * HD + threadIdx.x * 4;
    float4 v = *(const float4*)(q + base);
    float s = v.x * v.x + v.y * v.y + v.z * v.z + v.w * v.w;
    s = blk_reduce_256(s);
    if (threadIdx.x == 0) scale[blockIdx.x] = rsqrtf(s + 1e-6f) * 10.0f;
}

__global__ void round_copy(const float* __restrict__ in, float* __restrict__ out) {
    size_t i = ((size_t)blockIdx.x * 256 + threadIdx.x) * 4;
    float4 v = *(const float4*)(in + i);
    v.x = to_tf32(v.x); v.y = to_tf32(v.y); v.z = to_tf32(v.z); v.w = to_tf32(v.w);
    *(float4*)(out + i) = v;
}

// V[16384,1024] -> Vt[1024,16384], rounded
__global__ void transpose_rnd(const float* __restrict__ src, float* __restrict__ dst) {
    __shared__ float tl[32][33];
    int n0 = blockIdx.x * 32, k0 = blockIdx.y * 32;
    int tx = threadIdx.x, ty = threadIdx.y;
    #pragma unroll
    for (int j = 0; j < 4; j++)
        tl[ty + 8 * j][tx] = src[(size_t)(k0 + ty + 8 * j) * HD + n0 + tx];
    __syncthreads();
    #pragma unroll
    for (int j = 0; j < 4; j++)
        dst[(size_t)(n0 + ty + 8 * j) * MMSZ + k0 + tx] = to_tf32(tl[tx][ty + 8 * j]);
}

// ---------------------------------------------------------------------------

extern "C" void kernel_launch(void* const* d_in, const int* in_sizes, int n_in,
                              void* d_out, int out_size) {
    const float* hidden = (const float*)d_in[0];
    const float* Wk     = (const float*)d_in[1];
    const float* bk     = (const float*)d_in[2];
    const float* Wo     = (const float*)d_in[5];
    const float* bo     = (const float*)d_in[6];
    const float* mkeys  = (const float*)d_in[7];
    const float* mvals  = (const float*)d_in[8];
    const int*   usage  = (const int*)d_in[9];

    float *mkn, *q, *qs, *P, *rs, *ret, *vt, *ht, *wk, *wo;
    cudaGetSymbolAddress((void**)&mkn, g_mkn);
    cudaGetSymbolAddress((void**)&q,   g_q);
    cudaGetSymbolAddress((void**)&qs,  g_qs);
    cudaGetSymbolAddress((void**)&P,   g_P);
    cudaGetSymbolAddress((void**)&rs,  g_rs);
    cudaGetSymbolAddress((void**)&ret, g_ret);
    cudaGetSymbolAddress((void**)&vt,  g_vt);
    cudaGetSymbolAddress((void**)&ht,  g_ht);
    cudaGetSymbolAddress((void**)&wk,  g_wk);
    cudaGetSymbolAddress((void**)&wo,  g_wo);

    cudaFuncSetAttribute(gemm_mma<EPI_BIAS, true>,     cudaFuncAttributeMaxDynamicSharedMemorySize, SMEM_TOTAL);
    cudaFuncSetAttribute(gemm_mma<EPI_EXPMASK, true>,  cudaFuncAttributeMaxDynamicSharedMemorySize, SMEM_TOTAL);
    cudaFuncSetAttribute(gemm_mma<EPI_ROWSCALE, true>, cudaFuncAttributeMaxDynamicSharedMemorySize, SMEM_TOTAL);
    cudaFuncSetAttribute(gemm_mma<EPI_BIAS, false>,    cudaFuncAttributeMaxDynamicSharedMemorySize, SMEM_TOTAL);

    // producers: tf32-round every GEMM operand
    round_copy<<<(MQ * HD) / 1024, 256>>>(hidden, ht);
    round_copy<<<(HD * HD) / 1024, 256>>>(Wk, wk);
    round_copy<<<(HD * HD) / 1024, 256>>>(Wo, wo);
    row_l2norm_rnd<<<MMSZ, 256>>>(mkeys, mkn);
    transpose_rnd<<<dim3(HD / 32, MMSZ / 32), dim3(32, 8)>>>(mvals, vt);
    cudaMemsetAsync(rs, 0, MQ * sizeof(float));

    // K2: q = X @ Wk^T + bk  (rounded output)
    gemm_mma<EPI_BIAS, true><<<dim3(MQ / BM, HD / BN), 256, SMEM_TOTAL>>>(
        ht, wk, q, MQ, HD, HD, bk, nullptr, nullptr, 0);

    // K3: per-row query scale rsqrt(sumsq+eps)*10
    row_qscale<<<MQ, 256>>>(q, qs);

    // K4: P = mask ? exp(dot*qs - 10) : 0  (+fused rowsums, rounded output)
    gemm_mma<EPI_EXPMASK, true><<<dim3(MQ / BM, MMSZ / BN), 256, SMEM_TOTAL>>>(
        q, mkn, P, MQ, MMSZ, HD, qs, usage, rs, 0);

    // K6: ret = (P @ Vt^T) / rowsum  (rounded output; n-fastest grid)
    gemm_mma<EPI_ROWSCALE, true><<<dim3(HD / BN, MQ / BM), 256, SMEM_TOTAL>>>(
        P, vt, ret, MQ, HD, MMSZ, rs, nullptr, nullptr, 1);

    // K7: out = ret @ Wo^T + bo
    gemm_mma<EPI_BIAS, false><<<dim3(MQ / BM, HD / BN), 256, SMEM_TOTAL>>>(
        ret, wo, (float*)d_out, MQ, HD, HD, bo, nullptr, nullptr, 0);
}

// round 5
// speedup vs baseline: 3.4092x; 1.6863x over previous
#include <cuda_runtime.h>
#include <cstdint>

// ===========================================================================
// HierarchicalMemory via mma.sync tf32 (HMMA), with masked-slot compaction.
//   out = softmax_m(mask(qn.mkn/T)) @ V @ Wo^T + bo,  q = X@Wk^T + bk
// Fixed-offset softmax (|logit|<=10): P = exp(s-10), w = P/rowsum.
// All GEMM operands pre-rounded to tf32 (cvt.rna) -> HMMA truncation exact.
// Only active slots (usage>0, ~2/3 of 16384) participate: order-preserving
// compaction; padded columns are exact zeros.
// ===========================================================================

#define MQ   8192
#define HD   1024
#define MMSZ 16384

#define BM 128
#define BN 256
#define BK 16
#define STAGES 3
#define RSTRIDE 20                        // words per smem row (conflict-free)
#define ATILE_B (BM * RSTRIDE * 4)        // 10240
#define BTILE_B (BN * RSTRIDE * 4)        // 20480
#define STAGE_B (ATILE_B + BTILE_B)       // 30720
#define SMEM_TOTAL (STAGES * STAGE_B)     // 92160

// ---- scratch ----
__device__ float g_mkn[(size_t)MMSZ * HD];   // compacted, normalized, rounded
__device__ float g_q  [(size_t)MQ * HD];
__device__ float g_qs [MQ];
__device__ float g_P  [(size_t)MQ * MMSZ];
__device__ float g_rs [MQ];
__device__ float g_ret[(size_t)MQ * HD];
__device__ float g_vt [(size_t)HD * MMSZ];   // compacted columns, rounded
__device__ float g_ht [(size_t)MQ * HD];
__device__ float g_wk [(size_t)HD * HD];
__device__ float g_wo [(size_t)HD * HD];
__device__ int   g_idx[MMSZ];
__device__ int   g_mact;
__device__ int   g_mpad;

enum { EPI_BIAS = 0, EPI_EXPMASK = 1, EPI_ROWSCALE = 2 };

// ---------------------------------------------------------------------------
__device__ __forceinline__ uint32_t smem_u32(const void* p) {
    uint32_t a;
    asm("{ .reg .u64 t; cvta.to.shared.u64 t, %1; cvt.u32.u64 %0, t; }" : "=r"(a) : "l"(p));
    return a;
}
__device__ __forceinline__ float to_tf32(float x) {
    uint32_t u;
    asm("cvt.rna.tf32.f32 %0, %1;" : "=r"(u) : "f"(x));
    return __uint_as_float(u);
}
#define CP_ASYNC16(dst, src) \
    asm volatile("cp.async.cg.shared.global [%0], [%1], 16;" :: "r"(dst), "l"(src) : "memory")
#define CP_COMMIT() asm volatile("cp.async.commit_group;" ::: "memory")
#define CP_WAIT1()  asm volatile("cp.async.wait_group 1;" ::: "memory")

__device__ __forceinline__ void mma8(float* d, const uint32_t* a, const uint32_t* b) {
    asm volatile(
        "mma.sync.aligned.m16n8k8.row.col.f32.tf32.tf32.f32 "
        "{%0,%1,%2,%3}, {%4,%5,%6,%7}, {%8,%9}, {%0,%1,%2,%3};"
        : "+f"(d[0]), "+f"(d[1]), "+f"(d[2]), "+f"(d[3])
        : "r"(a[0]), "r"(a[1]), "r"(a[2]), "r"(a[3]), "r"(b[0]), "r"(b[1]));
}

// ---------------------------------------------------------------------------
// C[M,N] = A[M,K] . B[N,K]^T  (NT, K-major, tf32-rounded fp32)
// 8 warps in 2x4 grid, 64x64 warp tiles.
// DYNK: K bound read from g_mpad. EXPMASK: n-tiles >= g_mpad exit; columns
// >= g_mact masked to zero.  nx=1: blockIdx.x is the n-tile (L2 reuse).
// ---------------------------------------------------------------------------
template <int EPI, bool ROUND, bool DYNK>
__global__ __launch_bounds__(256)
void gemm_mma(const float* __restrict__ A, int lda,
              const float* __restrict__ B, int ldb,
              float* __restrict__ C, int ldc,
              int K, const float* __restrict__ aux,
              float* __restrict__ rowsum, int nx) {
    const int mtb = nx ? blockIdx.y : blockIdx.x;
    const int ntb = nx ? blockIdx.x : blockIdx.y;
    const int m0 = mtb * BM, n0 = ntb * BN;

    if (EPI == EPI_EXPMASK && n0 >= g_mpad) return;
    const int Keff = DYNK ? g_mpad : K;
    const int n_it = Keff / BK;

    extern __shared__ char smem[];
    const uint32_t sb = smem_u32(smem);
    const int tid  = threadIdx.x;
    const int wid  = tid >> 5, lane = tid & 31;
    const int g    = lane >> 2, t = lane & 3;
    const int wm   = wid >> 2, wn = wid & 3;      // 2 x 4 warps, 64x64 tiles

    float acc[4][8][4];
    #pragma unroll
    for (int i = 0; i < 4; i++)
        #pragma unroll
        for (int j = 0; j < 8; j++)
            #pragma unroll
            for (int r = 0; r < 4; r++) acc[i][j][r] = 0.0f;

    // loader mapping: A 128 rows x 4 chunks (2/thread), B 256 rows x 4 (4/thread)
    const int arow = tid >> 1;
    const int aq   = (tid & 1) * 2;

    auto issue = [&](int it) {
        if (it < n_it) {
            const int s = it % STAGES;
            const int kt = it * BK;
            const uint32_t da = sb + s * STAGE_B;
            const uint32_t db = da + ATILE_B;
            const float* ga = A + (size_t)(m0 + arow) * lda + kt;
            const float* gb = B + (size_t)(n0 + tid) * ldb + kt;
            #pragma unroll
            for (int c = 0; c < 2; c++)
                CP_ASYNC16(da + arow * (RSTRIDE * 4) + (aq + c) * 16, ga + (aq + c) * 4);
            #pragma unroll
            for (int c = 0; c < 4; c++)
                CP_ASYNC16(db + tid * (RSTRIDE * 4) + c * 16, gb + c * 4);
        }
        CP_COMMIT();
    };

    issue(0);
    issue(1);
    CP_WAIT1();
    __syncthreads();

    for (int it = 0; it < n_it; ++it) {
        issue(it + 2);     // writes slot (it-1)%3, already consumed by all

        const int s = it % STAGES;
        const uint32_t* As = (const uint32_t*)(smem + s * STAGE_B);
        const uint32_t* Bs = (const uint32_t*)(smem + s * STAGE_B + ATILE_B);

        #pragma unroll
        for (int kk = 0; kk < 2; kk++) {
            const int ko = kk * 8 + t;
            uint32_t af[4][4], bf[8][2];
            #pragma unroll
            for (int mt = 0; mt < 4; mt++) {
                const int base = (wm * 64 + mt * 16 + g) * RSTRIDE + ko;
                af[mt][0] = As[base];
                af[mt][1] = As[base + 8 * RSTRIDE];
                af[mt][2] = As[base + 4];
                af[mt][3] = As[base + 8 * RSTRIDE + 4];
            }
            #pragma unroll
            for (int nt = 0; nt < 8; nt++) {
                const int base = (wn * 64 + nt * 8 + g) * RSTRIDE + ko;
                bf[nt][0] = Bs[base];
                bf[nt][1] = Bs[base + 4];
            }
            #pragma unroll
            for (int mt = 0; mt < 4; mt++)
                #pragma unroll
                for (int nt = 0; nt < 8; nt++)
                    mma8(acc[mt][nt], af[mt], bf[nt]);
        }

        CP_WAIT1();
        __syncthreads();
    }

    // ---------------- epilogue ----------------
    const int mrow = m0 + wm * 64;
    const int ncol = n0 + wn * 64;
    const int mact = (EPI == EPI_EXPMASK) ? g_mact : 0;

    float bia[8][2];
    if (EPI == EPI_BIAS) {
        #pragma unroll
        for (int nt = 0; nt < 8; nt++) {
            const int c = ncol + nt * 8 + 2 * t;
            bia[nt][0] = __ldg(aux + c);
            bia[nt][1] = __ldg(aux + c + 1);
        }
    }
    float rsv[4][2];
    #pragma unroll
    for (int mt = 0; mt < 4; mt++)
        #pragma unroll
        for (int h = 0; h < 2; h++) {
            const int r = mrow + mt * 16 + g + h * 8;
            if (EPI == EPI_EXPMASK)  rsv[mt][h] = __ldg(aux + r);
            if (EPI == EPI_ROWSCALE) rsv[mt][h] = 1.0f / __ldg(aux + r);
        }

    float rsum[4][2];
    #pragma unroll
    for (int mt = 0; mt < 4; mt++) { rsum[mt][0] = 0.0f; rsum[mt][1] = 0.0f; }

    #pragma unroll
    for (int mt = 0; mt < 4; mt++) {
        #pragma unroll
        for (int h = 0; h < 2; h++) {
            const int r = mrow + mt * 16 + g + h * 8;
            float* crow = C + (size_t)r * ldc;
            #pragma unroll
            for (int nt = 0; nt < 8; nt++) {
                const int c = ncol + nt * 8 + 2 * t;
                float v0 = acc[mt][nt][2 * h + 0];
                float v1 = acc[mt][nt][2 * h + 1];
                if (EPI == EPI_BIAS) { v0 += bia[nt][0]; v1 += bia[nt][1]; }
                if (EPI == EPI_EXPMASK) {
                    const float rs = rsv[mt][h];
                    v0 = (c     < mact) ? __expf(fmaf(v0, rs, -10.0f)) : 0.0f;
                    v1 = (c + 1 < mact) ? __expf(fmaf(v1, rs, -10.0f)) : 0.0f;
                }
                if (EPI == EPI_ROWSCALE) { v0 *= rsv[mt][h]; v1 *= rsv[mt][h]; }
                if (ROUND) { v0 = to_tf32(v0); v1 = to_tf32(v1); }
                if (EPI == EPI_EXPMASK) rsum[mt][h] += v0 + v1;
                *(float2*)(crow + c) = make_float2(v0, v1);
            }
        }
    }

    if (EPI == EPI_EXPMASK) {
        #pragma unroll
        for (int mt = 0; mt < 4; mt++)
            #pragma unroll
            for (int h = 0; h < 2; h++) {
                float v = rsum[mt][h];
                v += __shfl_xor_sync(0xffffffffu, v, 1);
                v += __shfl_xor_sync(0xffffffffu, v, 2);
                if (t == 0) atomicAdd(rowsum + mrow + mt * 16 + g + h * 8, v);
            }
    }
}

// ---------------------------------------------------------------------------
// compaction: order-preserving scan of usage>0 into g_idx; sets g_mact/g_mpad
// ---------------------------------------------------------------------------
__global__ void compact_mask(const int* __restrict__ usage) {
    const int tid = threadIdx.x;
    const int base = tid * (MMSZ / 256);
    int cnt = 0;
    #pragma unroll 8
    for (int i = 0; i < MMSZ / 256; i++) cnt += (usage[base + i] > 0);
    int v = cnt;
    const int lane = tid & 31, w = tid >> 5;
    #pragma unroll
    for (int o = 1; o < 32; o <<= 1) {
        int n = __shfl_up_sync(0xffffffffu, v, o);
        if (lane >= o) v += n;
    }
    __shared__ int ws[8];
    if (lane == 31) ws[w] = v;
    __syncthreads();
    if (tid == 0) {
        int acc = 0;
        #pragma unroll
        for (int i = 0; i < 8; i++) { int x = ws[i]; ws[i] = acc; acc += x; }
        g_mact = acc;
        g_mpad = (acc + BN - 1) & ~(BN - 1);
    }
    __syncthreads();
    int off = ws[w] + v - cnt;
    for (int i = 0; i < MMSZ / 256; i++)
        if (usage[base + i] > 0) g_idx[off++] = base + i;
}

// ---------------------------------------------------------------------------
__device__ __forceinline__ float blk_reduce_256(float v) {
    #pragma unroll
    for (int o = 16; o > 0; o >>= 1) v += __shfl_xor_sync(0xffffffffu, v, o);
    __shared__ float sm[8];
    int w = threadIdx.x >> 5, l = threadIdx.x & 31;
    if (l == 0) sm[w] = v;
    __syncthreads();
    float r = 0.0f;
    if (w == 0) {
        r = (l < 8) ? sm[l] : 0.0f;
        #pragma unroll
        for (int o = 4; o > 0; o >>= 1) r += __shfl_xor_sync(0xffffffffu, r, o);
    }
    return r;
}

// mkn_c[j,:] = l2norm(mkeys[idx[j],:]) rounded; zeros for pad rows
__global__ void l2norm_gather(const float* __restrict__ in, float* __restrict__ out) {
    const int j = blockIdx.x;
    if (j >= g_mpad) return;
    const size_t doff = (size_t)j * HD + threadIdx.x * 4;
    if (j >= g_mact) { *(float4*)(out + doff) = make_float4(0.f, 0.f, 0.f, 0.f); return; }
    const size_t soff = (size_t)g_idx[j] * HD + threadIdx.x * 4;
    float4 v = *(const float4*)(in + soff);
    float s = v.x * v.x + v.y * v.y + v.z * v.z + v.w * v.w;
    s = blk_reduce_256(s);
    __shared__ float sc;
    if (threadIdx.x == 0) sc = rsqrtf(s + 1e-6f);
    __syncthreads();
    const float k = sc;
    v.x = to_tf32(v.x * k); v.y = to_tf32(v.y * k);
    v.z = to_tf32(v.z * k); v.w = to_tf32(v.w * k);
    *(float4*)(out + doff) = v;
}

// vt[h, j] = V[idx[j], h] rounded; zeros for pad columns
__global__ void transpose_gather(const float* __restrict__ src, float* __restrict__ dst) {
    __shared__ float tl[32][33];
    const int n0 = blockIdx.x * 32, k0 = blockIdx.y * 32;
    if (k0 >= g_mpad) return;
    const int tx = threadIdx.x, ty = threadIdx.y;
    const int mact = g_mact;
    #pragma unroll
    for (int j = 0; j < 4; j++) {
        const int k = k0 + ty + 8 * j;
        float v = 0.0f;
        if (k < mact) v = src[(size_t)g_idx[k] * HD + n0 + tx];
        tl[ty + 8 * j][tx] = v;
    }
    __syncthreads();
    #pragma unroll
    for (int j = 0; j < 4; j++)
        dst[(size_t)(n0 + ty + 8 * j) * MMSZ + k0 + tx] = to_tf32(tl[tx][ty + 8 * j]);
}

__global__ void row_qscale(const float* __restrict__ q, float* __restrict__ scale) {
    size_t base = (size_t)blockIdx.x * HD + threadIdx.x * 4;
    float4 v = *(const float4*)(q + base);
    float s = v.x * v.x + v.y * v.y + v.z * v.z + v.w * v.w;
    s = blk_reduce_256(s);
    if (threadIdx.x == 0) scale[blockIdx.x] = rsqrtf(s + 1e-6f) * 10.0f;
}

__global__ void round_copy(const float* __restrict__ in, float* __restrict__ out) {
    size_t i = ((size_t)blockIdx.x * 256 + threadIdx.x) * 4;
    float4 v = *(const float4*)(in + i);
    v.x = to_tf32(v.x); v.y = to_tf32(v.y); v.z = to_tf32(v.z); v.w = to_tf32(v.w);
    *(float4*)(out + i) = v;
}

// ---------------------------------------------------------------------------

extern "C" void kernel_launch(void* const* d_in, const int* in_sizes, int n_in,
                              void* d_out, int out_size) {
    const float* hidden = (const float*)d_in[0];
    const float* Wk     = (const float*)d_in[1];
    const float* bk     = (const float*)d_in[2];
    const float* Wo     = (const float*)d_in[5];
    const float* bo     = (const float*)d_in[6];
    const float* mkeys  = (const float*)d_in[7];
    const float* mvals  = (const float*)d_in[8];
    const int*   usage  = (const int*)d_in[9];

    float *mkn, *q, *qs, *P, *rs, *ret, *vt, *ht, *wk, *wo;
    cudaGetSymbolAddress((void**)&mkn, g_mkn);
    cudaGetSymbolAddress((void**)&q,   g_q);
    cudaGetSymbolAddress((void**)&qs,  g_qs);
    cudaGetSymbolAddress((void**)&P,   g_P);
    cudaGetSymbolAddress((void**)&rs,  g_rs);
    cudaGetSymbolAddress((void**)&ret, g_ret);
    cudaGetSymbolAddress((void**)&vt,  g_vt);
    cudaGetSymbolAddress((void**)&ht,  g_ht);
    cudaGetSymbolAddress((void**)&wk,  g_wk);
    cudaGetSymbolAddress((void**)&wo,  g_wo);

    cudaFuncSetAttribute(gemm_mma<EPI_BIAS, true, false>,    cudaFuncAttributeMaxDynamicSharedMemorySize, SMEM_TOTAL);
    cudaFuncSetAttribute(gemm_mma<EPI_EXPMASK, true, false>, cudaFuncAttributeMaxDynamicSharedMemorySize, SMEM_TOTAL);
    cudaFuncSetAttribute(gemm_mma<EPI_ROWSCALE, true, true>, cudaFuncAttributeMaxDynamicSharedMemorySize, SMEM_TOTAL);
    cudaFuncSetAttribute(gemm_mma<EPI_BIAS, false, false>,   cudaFuncAttributeMaxDynamicSharedMemorySize, SMEM_TOTAL);

    // compaction + operand preparation (all GEMM operands tf32-rounded)
    compact_mask<<<1, 256>>>(usage);
    round_copy<<<(MQ * HD) / 1024, 256>>>(hidden, ht);
    round_copy<<<(HD * HD) / 1024, 256>>>(Wk, wk);
    round_copy<<<(HD * HD) / 1024, 256>>>(Wo, wo);
    l2norm_gather<<<MMSZ, 256>>>(mkeys, mkn);
    transpose_gather<<<dim3(HD / 32, MMSZ / 32), dim3(32, 8)>>>(mvals, vt);
    cudaMemsetAsync(rs, 0, MQ * sizeof(float));

    // K2: q = X @ Wk^T + bk  (rounded output)
    gemm_mma<EPI_BIAS, true, false><<<dim3(MQ / BM, HD / BN), 256, SMEM_TOTAL>>>(
        ht, HD, wk, HD, q, HD, HD, bk, nullptr, 0);

    // K3: per-row query scale rsqrt(sumsq+eps)*10
    row_qscale<<<MQ, 256>>>(q, qs);

    // K4: P = (col<mact) ? exp(dot*qs - 10) : 0  (+fused rowsums, rounded)
    gemm_mma<EPI_EXPMASK, true, false><<<dim3(MQ / BM, MMSZ / BN), 256, SMEM_TOTAL>>>(
        q, HD, mkn, HD, P, MMSZ, HD, qs, rs, 0);

    // K6: ret = (P @ Vt^T) / rowsum  (dynamic K = mpad; n-fastest grid)
    gemm_mma<EPI_ROWSCALE, true, true><<<dim3(HD / BN, MQ / BM), 256, SMEM_TOTAL>>>(
        P, MMSZ, vt, MMSZ, ret, HD, MMSZ, rs, nullptr, 1);

    // K7: out = ret @ Wo^T + bo
    gemm_mma<EPI_BIAS, false, false><<<dim3(MQ / BM, HD / BN), 256, SMEM_TOTAL>>>(
        ret, HD, wo, HD, (float*)d_out, HD, HD, bo, nullptr, 0);
}